// round 3
// baseline (speedup 1.0000x reference)
#include <cuda_runtime.h>

#define BATCH 64
#define PIX   196
#define ENCD  2048
#define ATTD  512
#define DECD  512
#define EMBD  512
#define TT    32
#define NSTEP 31
#define VOC   30000
#define XH_W  3072   // layout per batch row: emb[512] | context[2048] | h[512]
#define GATE_N 1536

// ---------------- device scratch (static: no allocs allowed) ----------------
__device__ float g_att1[(size_t)BATCH * PIX * ATTD];   // 25.7 MB
__device__ float g_xh[BATCH * XH_W];                   // x=[emb,ctx] and h
__device__ float g_gates[2 * BATCH * GATE_N];          // [0]=gi, [1]=gh
__device__ float g_hall[(size_t)NSTEP * BATCH * DECD]; // h after each step

// ---------------- utility ----------------
__global__ void zerok(float* p, int n) {
    int i = blockIdx.x * blockDim.x + threadIdx.x;
    if (i < n) p[i] = 0.f;
}

// ---------------- generic 128x128x16 fp32 GEMM: C = A * B^T + bias --------
// A [M,K] row-major (lda), B [N,K] row-major (ldb), bias[N].
// REMAP=1: row m = t*64+b -> store at ((b*31+t)*VOC + n)   (logits layout)
template <int REMAP>
__global__ __launch_bounds__(256) void gemm128(
    const float* __restrict__ A, int lda,
    const float* __restrict__ Bm, int ldb,
    const float* __restrict__ bias, float* __restrict__ C,
    int M, int N, int K)
{
    __shared__ float sA[128][17];
    __shared__ float sBt[16][132];
    const int tid = threadIdx.x;
    const int m0 = blockIdx.x * 128;
    const int n0 = blockIdx.y * 128;
    const int ty = tid >> 4;   // 0..15
    const int tx = tid & 15;   // 0..15

    float acc[8][8];
#pragma unroll
    for (int i = 0; i < 8; i++)
#pragma unroll
        for (int j = 0; j < 8; j++) acc[i][j] = 0.f;

    for (int kc = 0; kc < K; kc += 16) {
#pragma unroll
        for (int i = tid; i < 2048; i += 256) {
            int r = i >> 4, c = i & 15;
            int gm = m0 + r;
            sA[r][c] = (gm < M) ? A[(size_t)gm * lda + kc + c] : 0.f;
        }
#pragma unroll
        for (int i = tid; i < 2048; i += 256) {
            int r = i >> 4, c = i & 15;
            int gn = n0 + r;
            sBt[c][r] = (gn < N) ? Bm[(size_t)gn * ldb + kc + c] : 0.f;
        }
        __syncthreads();
#pragma unroll
        for (int k = 0; k < 16; k++) {
            float a[8];
#pragma unroll
            for (int i = 0; i < 8; i++) a[i] = sA[ty * 8 + i][k];
            float4 b0 = *(const float4*)&sBt[k][tx * 8];
            float4 b1 = *(const float4*)&sBt[k][tx * 8 + 4];
            float b[8] = {b0.x, b0.y, b0.z, b0.w, b1.x, b1.y, b1.z, b1.w};
#pragma unroll
            for (int i = 0; i < 8; i++)
#pragma unroll
                for (int j = 0; j < 8; j++) acc[i][j] += a[i] * b[j];
        }
        __syncthreads();
    }

#pragma unroll
    for (int i = 0; i < 8; i++) {
        int gm = m0 + ty * 8 + i;
        if (gm >= M) continue;
#pragma unroll
        for (int j = 0; j < 8; j++) {
            int gn = n0 + tx * 8 + j;
            if (gn >= N) continue;
            float v = acc[i][j] + bias[gn];
            if (REMAP) {
                int t = gm >> 6, b = gm & 63;
                C[((size_t)b * NSTEP + t) * VOC + gn] = v;
            } else {
                C[(size_t)gm * N + gn] = v;
            }
        }
    }
}

// ---------------- split-K GEMM for GRU gates (M fixed = 64) ----------------
// C[64,N] += A[64,K] * B[N,K]^T  (atomicAdd accumulation, C pre-zeroed)
__global__ __launch_bounds__(128) void gemm_splitk(
    const float* __restrict__ A, int lda,
    const float* __restrict__ Bm, int ldb,
    float* __restrict__ C, int ldc,
    int K, int nsplit)
{
    __shared__ float sA[64][17];
    __shared__ float sBt[16][68];
    const int tid = threadIdx.x;
    const int n0 = blockIdx.x * 64;
    const int z = blockIdx.z;
    const int chunks = (K / 16) / nsplit;
    const int k_begin = z * chunks * 16;
    const int k_end = k_begin + chunks * 16;
    const int tr = (tid >> 3) << 2;  // 0,4,...,60
    const int tc = (tid & 7) << 3;   // 0,8,...,56

    float acc[4][8];
#pragma unroll
    for (int i = 0; i < 4; i++)
#pragma unroll
        for (int j = 0; j < 8; j++) acc[i][j] = 0.f;

    for (int kc = k_begin; kc < k_end; kc += 16) {
#pragma unroll
        for (int i = tid; i < 1024; i += 128) {
            int r = i >> 4, c = i & 15;
            sA[r][c] = A[(size_t)r * lda + kc + c];
            sBt[c][r] = Bm[(size_t)(n0 + r) * ldb + kc + c];
        }
        __syncthreads();
#pragma unroll
        for (int k = 0; k < 16; k++) {
            float a0 = sA[tr][k], a1 = sA[tr + 1][k];
            float a2 = sA[tr + 2][k], a3 = sA[tr + 3][k];
            float4 b0 = *(const float4*)&sBt[k][tc];
            float4 b1 = *(const float4*)&sBt[k][tc + 4];
            float b[8] = {b0.x, b0.y, b0.z, b0.w, b1.x, b1.y, b1.z, b1.w};
#pragma unroll
            for (int j = 0; j < 8; j++) {
                acc[0][j] += a0 * b[j];
                acc[1][j] += a1 * b[j];
                acc[2][j] += a2 * b[j];
                acc[3][j] += a3 * b[j];
            }
        }
        __syncthreads();
    }
#pragma unroll
    for (int i = 0; i < 4; i++)
#pragma unroll
        for (int j = 0; j < 8; j++)
            atomicAdd(&C[(size_t)(tr + i) * ldc + n0 + tc + j], acc[i][j]);
}

// ---------------- fused attention step (one block per batch element) -------
__global__ __launch_bounds__(256) void attention_step(
    int t,
    const float* __restrict__ enc,
    const int* __restrict__ captions,
    const float* __restrict__ emb_table,
    const float* __restrict__ W_dec, const float* __restrict__ b_dec,
    const float* __restrict__ w_full, const float* __restrict__ b_full)
{
    const int b = blockIdx.x;
    const int tid = threadIdx.x;
    const int lane = tid & 31, warp = tid >> 5;
    __shared__ float sh[DECD];
    __shared__ float satt2[ATTD];
    __shared__ float se[PIX];
    __shared__ float sred[16];
    float* xh = g_xh + b * XH_W;

    for (int i = tid; i < DECD; i += 256) sh[i] = xh[2560 + i];
    __syncthreads();

    // att2 = h @ W_dec^T + b_dec : warp per output, lane-strided K
    for (int a = warp; a < ATTD; a += 8) {
        const float* wr = W_dec + (size_t)a * DECD;
        float s = 0.f;
        for (int k = lane; k < DECD; k += 32) s += sh[k] * wr[k];
#pragma unroll
        for (int o = 16; o; o >>= 1) s += __shfl_xor_sync(0xffffffffu, s, o);
        if (lane == 0) satt2[a] = s + b_dec[a];
    }
    __syncthreads();

    // scores e[p] = sum_a tanh(att1 + att2) * w_full + b_full
    const float* att1b = g_att1 + (size_t)b * PIX * ATTD;
    for (int p = warp; p < PIX; p += 8) {
        const float* ar = att1b + (size_t)p * ATTD;
        float s = 0.f;
        for (int a = lane; a < ATTD; a += 32)
            s += tanhf(ar[a] + satt2[a]) * w_full[a];
#pragma unroll
        for (int o = 16; o; o >>= 1) s += __shfl_xor_sync(0xffffffffu, s, o);
        if (lane == 0) se[p] = s + b_full[0];
    }
    __syncthreads();

    // softmax over 196
    float lm = -3.4e38f;
    for (int p = tid; p < PIX; p += 256) lm = fmaxf(lm, se[p]);
#pragma unroll
    for (int o = 16; o; o >>= 1) lm = fmaxf(lm, __shfl_xor_sync(0xffffffffu, lm, o));
    if (lane == 0) sred[warp] = lm;
    __syncthreads();
    if (warp == 0) {
        float v = (lane < 8) ? sred[lane] : -3.4e38f;
#pragma unroll
        for (int o = 16; o; o >>= 1) v = fmaxf(v, __shfl_xor_sync(0xffffffffu, v, o));
        if (lane == 0) sred[8] = v;
    }
    __syncthreads();
    const float gmax = sred[8];
    float ls = 0.f;
    for (int p = tid; p < PIX; p += 256) {
        float ex = expf(se[p] - gmax);
        se[p] = ex;
        ls += ex;
    }
#pragma unroll
    for (int o = 16; o; o >>= 1) ls += __shfl_xor_sync(0xffffffffu, ls, o);
    if (lane == 0) sred[warp] = ls;
    __syncthreads();
    if (warp == 0) {
        float v = (lane < 8) ? sred[lane] : 0.f;
#pragma unroll
        for (int o = 16; o; o >>= 1) v += __shfl_xor_sync(0xffffffffu, v, o);
        if (lane == 0) sred[9] = v;
    }
    __syncthreads();
    const float sinv = 1.f / sred[9];

    // context[j] = sum_p alpha[p] * enc[b,p,j]  (ENCD = 8*256 exactly)
    const float* encb = enc + (size_t)b * PIX * ENCD;
    float c[8];
#pragma unroll
    for (int i = 0; i < 8; i++) c[i] = 0.f;
    for (int p = 0; p < PIX; p++) {
        const float ap = se[p];
        const float* row = encb + (size_t)p * ENCD;
#pragma unroll
        for (int i = 0; i < 8; i++) c[i] += ap * row[tid + (i << 8)];
    }
#pragma unroll
    for (int i = 0; i < 8; i++) xh[512 + tid + (i << 8)] = c[i] * sinv;

    // embedding for this step into x[0:512]
    const int cap = captions[b * TT + t];
    const float* er = emb_table + (size_t)cap * EMBD;
    for (int j = tid; j < EMBD; j += 256) xh[j] = er[j];
}

// ---------------- GRU gate activations + h update --------------------------
__global__ __launch_bounds__(256) void gru_gates(
    int t, const float* __restrict__ b_ih, const float* __restrict__ b_hh)
{
    int idx = blockIdx.x * 256 + threadIdx.x;
    if (idx >= BATCH * DECD) return;
    int b = idx >> 9, d = idx & 511;
    const float* gi = g_gates + (size_t)b * GATE_N;
    const float* gh = g_gates + (size_t)BATCH * GATE_N + (size_t)b * GATE_N;
    float rr = (gi[d] + b_ih[d]) + (gh[d] + b_hh[d]);
    float zz = (gi[512 + d] + b_ih[512 + d]) + (gh[512 + d] + b_hh[512 + d]);
    float inp = gi[1024 + d] + b_ih[1024 + d];
    float hnp = gh[1024 + d] + b_hh[1024 + d];
    float r = 1.f / (1.f + expf(-rr));
    float z = 1.f / (1.f + expf(-zz));
    float n = tanhf(inp + r * hnp);
    float* xh = g_xh + (size_t)b * XH_W;
    float hold = xh[2560 + d];
    float hnew = (1.f - z) * n + z * hold;
    xh[2560 + d] = hnew;
    g_hall[((size_t)t * BATCH + b) * DECD + d] = hnew;
}

__global__ void write_caplens(const int* __restrict__ caplens, float* __restrict__ out, int n)
{
    int i = threadIdx.x;
    if (i < n && i < BATCH) out[i] = (float)(caplens[i] - 1);
}

// ---------------- host ----------------
extern "C" void kernel_launch(void* const* d_in, const int* in_sizes, int n_in,
                              void* d_out, int out_size)
{
    const float* enc       = (const float*)d_in[0];
    const int*   captions  = (const int*)  d_in[1];
    const int*   caplens   = (const int*)  d_in[2];
    const float* emb_table = (const float*)d_in[3];
    const float* W_enc     = (const float*)d_in[4];
    const float* b_enc     = (const float*)d_in[5];
    const float* W_dec     = (const float*)d_in[6];
    const float* b_dec     = (const float*)d_in[7];
    const float* w_full    = (const float*)d_in[8];
    const float* b_full    = (const float*)d_in[9];
    const float* W_ih      = (const float*)d_in[10];
    const float* b_ih      = (const float*)d_in[11];
    const float* W_hh      = (const float*)d_in[12];
    const float* b_hh      = (const float*)d_in[13];
    const float* W_fc      = (const float*)d_in[14];
    const float* b_fc      = (const float*)d_in[15];
    float* out = (float*)d_out;

    float *att1p, *xhp, *gatesp, *hallp;
    cudaGetSymbolAddress((void**)&att1p, g_att1);
    cudaGetSymbolAddress((void**)&xhp, g_xh);
    cudaGetSymbolAddress((void**)&gatesp, g_gates);
    cudaGetSymbolAddress((void**)&hallp, g_hall);
    float* gip = gatesp;
    float* ghp = gatesp + BATCH * GATE_N;

    // h0 = 0 (zero entire xh; emb/context regions rewritten every step)
    zerok<<<(BATCH * XH_W + 255) / 256, 256>>>(xhp, BATCH * XH_W);

    // att1 = enc @ W_enc^T + b_enc : [12544,2048]x[2048,512]
    gemm128<0><<<dim3(98, 4), 256>>>(enc, ENCD, W_enc, ENCD, b_enc, att1p,
                                     BATCH * PIX, ATTD, ENCD);

    for (int t = 0; t < NSTEP; t++) {
        attention_step<<<BATCH, 256>>>(t, enc, captions, emb_table,
                                       W_dec, b_dec, w_full, b_full);
        zerok<<<(2 * BATCH * GATE_N + 255) / 256, 256>>>(gatesp, 2 * BATCH * GATE_N);
        // gi = x @ W_ih^T  (K=2560, 8-way split-K)
        gemm_splitk<<<dim3(24, 1, 8), 128>>>(xhp, XH_W, W_ih, 2560, gip, GATE_N, 2560, 8);
        // gh = h @ W_hh^T  (K=512, 4-way split-K)
        gemm_splitk<<<dim3(24, 1, 4), 128>>>(xhp + 2560, XH_W, W_hh, 512, ghp, GATE_N, 512, 4);
        gru_gates<<<(BATCH * DECD + 255) / 256, 256>>>(t, b_ih, b_hh);
    }

    // logits = h_all @ W_fc^T + b_fc, stored as [b, t, v]
    gemm128<1><<<dim3(16, 235), 256>>>(hallp, DECD, W_fc, DECD, b_fc, out,
                                       NSTEP * BATCH, VOC, DECD);

    long long NLOG = (long long)BATCH * NSTEP * VOC;
    if ((long long)out_size > NLOG) {
        int rem = (int)((long long)out_size - NLOG);
        write_caplens<<<1, 64>>>(caplens, out + NLOG, rem);
    }
}

// round 4
// speedup vs baseline: 3.6145x; 3.6145x over previous
#include <cuda_runtime.h>

#define BATCH 64
#define PIX   196
#define ENCD  2048
#define ATTD  512
#define DECD  512
#define EMBD  512
#define TT    32
#define NSTEP 31
#define VOC   30000
#define XH_W  3072   // per batch row: emb[512] | context[2048] | h[512]
#define GATE_N 1536

// ---------------- device scratch (static: no allocs allowed) ----------------
__device__ float g_att1[(size_t)BATCH * PIX * ATTD];   // 25.7 MB
__device__ float g_xh[BATCH * XH_W];
__device__ float g_gates[2 * BATCH * GATE_N];          // [0]=gi, [1]=gh
__device__ float g_hall[(size_t)NSTEP * BATCH * DECD];

// ---------------- utility ----------------
__global__ void zerok(float* p, int n) {
    int i = blockIdx.x * blockDim.x + threadIdx.x;
    if (i < n) p[i] = 0.f;
}

__device__ __forceinline__ unsigned int f2tf32(float f) {
    unsigned int r;
    asm("cvt.rna.tf32.f32 %0, %1;" : "=r"(r) : "f"(f));
    return r;
}

__device__ __forceinline__ void mma_tf32(float* c,
    unsigned int a0, unsigned int a1, unsigned int a2, unsigned int a3,
    unsigned int b0, unsigned int b1)
{
    asm("mma.sync.aligned.m16n8k8.row.col.f32.tf32.tf32.f32 "
        "{%0,%1,%2,%3}, {%4,%5,%6,%7}, {%8,%9}, {%0,%1,%2,%3};"
        : "+f"(c[0]), "+f"(c[1]), "+f"(c[2]), "+f"(c[3])
        : "r"(a0), "r"(a1), "r"(a2), "r"(a3), "r"(b0), "r"(b1));
}

// ---------------- tf32 tensor-core GEMM: C = A * B^T + bias ----------------
// Tile 128(M) x 64(N), K-step 32. 256 threads = 8 warps (4m x 2n), warp tile 32x32.
// A [M,K] row-major, B [N,K] row-major.
// REMAP=1: row m = t*64+b -> C[((b*31+t)*VOC + n)]
template <int REMAP>
__global__ __launch_bounds__(256) void gemm_tf32(
    const float* __restrict__ A, int lda,
    const float* __restrict__ Bm, int ldb,
    const float* __restrict__ bias, float* __restrict__ C,
    int M, int N, int K)
{
    __shared__ unsigned int sA[128][36];   // [row][k], pad 36 -> conflict-free frag reads
    __shared__ unsigned int sB[64][36];    // [n][k]
    const int tid = threadIdx.x;
    const int warp = tid >> 5, lane = tid & 31;
    const int m0 = blockIdx.x * 128, n0 = blockIdx.y * 64;
    const int wm = (warp >> 1) * 32;       // 0,32,64,96
    const int wn = (warp & 1) * 32;        // 0,32
    const int gid = lane >> 2;             // 0..7
    const int tig = lane & 3;              // 0..3

    float acc[2][4][4];
#pragma unroll
    for (int mt = 0; mt < 2; mt++)
#pragma unroll
        for (int nt = 0; nt < 4; nt++)
#pragma unroll
            for (int r = 0; r < 4; r++) acc[mt][nt][r] = 0.f;

    for (int kc = 0; kc < K; kc += 32) {
        // A-tile fill: 128x32 floats = 1024 float4, 4 per thread
#pragma unroll
        for (int v = tid; v < 1024; v += 256) {
            int row = v >> 3, c4 = v & 7;
            int gm = m0 + row;
            float4 f = make_float4(0.f, 0.f, 0.f, 0.f);
            if (gm < M) f = *(const float4*)&A[(size_t)gm * lda + kc + c4 * 4];
            unsigned int* d = &sA[row][c4 * 4];
            d[0] = f2tf32(f.x); d[1] = f2tf32(f.y);
            d[2] = f2tf32(f.z); d[3] = f2tf32(f.w);
        }
        // B-tile fill: 64x32 floats = 512 float4, 2 per thread
#pragma unroll
        for (int v = tid; v < 512; v += 256) {
            int row = v >> 3, c4 = v & 7;
            int gn = n0 + row;
            float4 f = make_float4(0.f, 0.f, 0.f, 0.f);
            if (gn < N) f = *(const float4*)&Bm[(size_t)gn * ldb + kc + c4 * 4];
            unsigned int* d = &sB[row][c4 * 4];
            d[0] = f2tf32(f.x); d[1] = f2tf32(f.y);
            d[2] = f2tf32(f.z); d[3] = f2tf32(f.w);
        }
        __syncthreads();
#pragma unroll
        for (int k8 = 0; k8 < 4; k8++) {
            const int kb = k8 * 8;
            unsigned int b0[4], b1[4];
#pragma unroll
            for (int nt = 0; nt < 4; nt++) {
                int rB = wn + nt * 8 + gid;
                b0[nt] = sB[rB][kb + tig];
                b1[nt] = sB[rB][kb + tig + 4];
            }
#pragma unroll
            for (int mt = 0; mt < 2; mt++) {
                int rA = wm + mt * 16 + gid;
                unsigned int a0 = sA[rA][kb + tig];
                unsigned int a1 = sA[rA + 8][kb + tig];
                unsigned int a2 = sA[rA][kb + tig + 4];
                unsigned int a3 = sA[rA + 8][kb + tig + 4];
#pragma unroll
                for (int nt = 0; nt < 4; nt++)
                    mma_tf32(acc[mt][nt], a0, a1, a2, a3, b0[nt], b1[nt]);
            }
        }
        __syncthreads();
    }

    // Epilogue: c0,c1 -> row gid; c2,c3 -> row gid+8; cols 2*tig, 2*tig+1.
#pragma unroll
    for (int mt = 0; mt < 2; mt++) {
#pragma unroll
        for (int half = 0; half < 2; half++) {
            int gm = m0 + wm + mt * 16 + gid + half * 8;
            if (gm >= M) continue;
#pragma unroll
            for (int nt = 0; nt < 4; nt++) {
                int gn = n0 + wn + nt * 8 + tig * 2;
                float v0 = acc[mt][nt][half * 2 + 0];
                float v1 = acc[mt][nt][half * 2 + 1];
                if (REMAP) {
                    int t = gm >> 6, bb = gm & 63;
                    size_t base = ((size_t)bb * NSTEP + t) * VOC;
                    if (gn < N)     C[base + gn]     = v0 + bias[gn];
                    if (gn + 1 < N) C[base + gn + 1] = v1 + bias[gn + 1];
                } else {
                    size_t base = (size_t)gm * N;
                    if (gn < N)     C[base + gn]     = v0 + bias[gn];
                    if (gn + 1 < N) C[base + gn + 1] = v1 + bias[gn + 1];
                }
            }
        }
    }
}

// ---------------- merged split-K GEMMs for GRU gates -----------------------
// blockIdx.y==0: gi = x  @ W_ih^T  (K=2560, 10-way split)
// blockIdx.y==1: gh = h  @ W_hh^T  (K=512,  8-way split)
// C accumulated with atomicAdd; zeroed by attention_step each step.
__global__ __launch_bounds__(128) void gru_gemms(
    const float* __restrict__ xh_base,
    const float* __restrict__ W_ih, const float* __restrict__ W_hh)
{
    const int y = blockIdx.y;
    const int nsplit = y ? 8 : 10;
    const int z = blockIdx.z;
    if (z >= nsplit) return;
    const float* A  = y ? xh_base + 2560 : xh_base;
    const float* Bm = y ? W_hh : W_ih;
    const int ldb = y ? 512 : 2560;
    const int K   = y ? 512 : 2560;
    float* C = g_gates + (y ? (size_t)BATCH * GATE_N : 0);
    const int chunks = (K / 16) / nsplit;   // 4 or 16
    const int k_begin = z * chunks * 16;
    const int k_end = k_begin + chunks * 16;

    __shared__ float sA[64][17];
    __shared__ float sBt[16][68];
    const int tid = threadIdx.x;
    const int n0 = blockIdx.x * 64;
    const int tr = (tid >> 3) << 2;  // 0,4,...,60
    const int tc = (tid & 7) << 3;   // 0,8,...,56

    float acc[4][8];
#pragma unroll
    for (int i = 0; i < 4; i++)
#pragma unroll
        for (int j = 0; j < 8; j++) acc[i][j] = 0.f;

    for (int kc = k_begin; kc < k_end; kc += 16) {
#pragma unroll
        for (int v = tid; v < 256; v += 128) {
            int row = v >> 2, c4 = v & 3;
            float4 fa = *(const float4*)&A[(size_t)row * XH_W + kc + c4 * 4];
            sA[row][c4 * 4 + 0] = fa.x; sA[row][c4 * 4 + 1] = fa.y;
            sA[row][c4 * 4 + 2] = fa.z; sA[row][c4 * 4 + 3] = fa.w;
            float4 fb = *(const float4*)&Bm[(size_t)(n0 + row) * ldb + kc + c4 * 4];
            sBt[c4 * 4 + 0][row] = fb.x; sBt[c4 * 4 + 1][row] = fb.y;
            sBt[c4 * 4 + 2][row] = fb.z; sBt[c4 * 4 + 3][row] = fb.w;
        }
        __syncthreads();
#pragma unroll
        for (int k = 0; k < 16; k++) {
            float a0 = sA[tr][k], a1 = sA[tr + 1][k];
            float a2 = sA[tr + 2][k], a3 = sA[tr + 3][k];
            float4 b0 = *(const float4*)&sBt[k][tc];
            float4 b1 = *(const float4*)&sBt[k][tc + 4];
            float bb[8] = {b0.x, b0.y, b0.z, b0.w, b1.x, b1.y, b1.z, b1.w};
#pragma unroll
            for (int j = 0; j < 8; j++) {
                acc[0][j] += a0 * bb[j];
                acc[1][j] += a1 * bb[j];
                acc[2][j] += a2 * bb[j];
                acc[3][j] += a3 * bb[j];
            }
        }
        __syncthreads();
    }
#pragma unroll
    for (int i = 0; i < 4; i++)
#pragma unroll
        for (int j = 0; j < 8; j++)
            atomicAdd(&C[(size_t)(tr + i) * GATE_N + n0 + tc + j], acc[i][j]);
}

// ---------------- fused attention step (one block per batch element) -------
__global__ __launch_bounds__(256) void attention_step(
    int t,
    const float* __restrict__ enc,
    const int* __restrict__ captions,
    const float* __restrict__ emb_table,
    const float* __restrict__ W_dec, const float* __restrict__ b_dec,
    const float* __restrict__ w_full, const float* __restrict__ b_full)
{
    const int b = blockIdx.x;
    const int tid = threadIdx.x;
    const int lane = tid & 31, warp = tid >> 5;
    __shared__ __align__(16) float sh[DECD];
    __shared__ __align__(16) float satt2[ATTD];
    __shared__ __align__(16) float se[PIX];
    __shared__ float sred[16];
    float* xh = g_xh + (size_t)b * XH_W;

    // zero this batch's gate accumulators (replaces a separate zerok launch)
    {
        float* gi = g_gates + (size_t)b * GATE_N;
        float* gh = g_gates + (size_t)BATCH * GATE_N + (size_t)b * GATE_N;
        for (int i = tid; i < GATE_N; i += 256) { gi[i] = 0.f; gh[i] = 0.f; }
    }

    for (int i = tid; i < DECD; i += 256) sh[i] = xh[2560 + i];
    __syncthreads();

    // att2 = h @ W_dec^T + b_dec  (warp per output, vectorized)
    const float4* shv = (const float4*)sh;
    for (int a = warp; a < ATTD; a += 8) {
        const float4* wr = (const float4*)(W_dec + (size_t)a * DECD);
        float s = 0.f;
#pragma unroll
        for (int k = lane; k < 128; k += 32) {
            float4 w = wr[k]; float4 h4 = shv[k];
            s += w.x * h4.x + w.y * h4.y + w.z * h4.z + w.w * h4.w;
        }
#pragma unroll
        for (int o = 16; o; o >>= 1) s += __shfl_xor_sync(0xffffffffu, s, o);
        if (lane == 0) satt2[a] = s + b_dec[a];
    }
    __syncthreads();

    // scores e[p] = tanh(att1 + att2) . w_full + b_full
    const float* att1b = g_att1 + (size_t)b * PIX * ATTD;
    const float4* satt2v = (const float4*)satt2;
    const float4* wfv = (const float4*)w_full;
    for (int p = warp; p < PIX; p += 8) {
        const float4* ar = (const float4*)(att1b + (size_t)p * ATTD);
        float s = 0.f;
#pragma unroll
        for (int a = lane; a < 128; a += 32) {
            float4 x = ar[a]; float4 t2 = satt2v[a]; float4 w = wfv[a];
            s += tanhf(x.x + t2.x) * w.x + tanhf(x.y + t2.y) * w.y
               + tanhf(x.z + t2.z) * w.z + tanhf(x.w + t2.w) * w.w;
        }
#pragma unroll
        for (int o = 16; o; o >>= 1) s += __shfl_xor_sync(0xffffffffu, s, o);
        if (lane == 0) se[p] = s + b_full[0];
    }
    __syncthreads();

    // softmax over 196
    float lm = -3.4e38f;
    for (int p = tid; p < PIX; p += 256) lm = fmaxf(lm, se[p]);
#pragma unroll
    for (int o = 16; o; o >>= 1) lm = fmaxf(lm, __shfl_xor_sync(0xffffffffu, lm, o));
    if (lane == 0) sred[warp] = lm;
    __syncthreads();
    if (warp == 0) {
        float v = (lane < 8) ? sred[lane] : -3.4e38f;
#pragma unroll
        for (int o = 16; o; o >>= 1) v = fmaxf(v, __shfl_xor_sync(0xffffffffu, v, o));
        if (lane == 0) sred[8] = v;
    }
    __syncthreads();
    const float gmax = sred[8];
    float ls = 0.f;
    for (int p = tid; p < PIX; p += 256) {
        float ex = expf(se[p] - gmax);
        se[p] = ex;
        ls += ex;
    }
#pragma unroll
    for (int o = 16; o; o >>= 1) ls += __shfl_xor_sync(0xffffffffu, ls, o);
    if (lane == 0) sred[warp] = ls;
    __syncthreads();
    if (warp == 0) {
        float v = (lane < 8) ? sred[lane] : 0.f;
#pragma unroll
        for (int o = 16; o; o >>= 1) v += __shfl_xor_sync(0xffffffffu, v, o);
        if (lane == 0) sred[9] = v;
    }
    __syncthreads();
    const float sinv = 1.f / sred[9];

    // context = alpha . enc  (vectorized: 2 float4 per thread)
    const float4* encb = (const float4*)(enc + (size_t)b * PIX * ENCD);
    float4 c0 = make_float4(0.f, 0.f, 0.f, 0.f);
    float4 c1 = make_float4(0.f, 0.f, 0.f, 0.f);
    for (int p = 0; p < PIX; p++) {
        const float ap = se[p];
        const float4* row = encb + (size_t)p * 512;
        float4 v0 = row[tid], v1 = row[tid + 256];
        c0.x += ap * v0.x; c0.y += ap * v0.y; c0.z += ap * v0.z; c0.w += ap * v0.w;
        c1.x += ap * v1.x; c1.y += ap * v1.y; c1.z += ap * v1.z; c1.w += ap * v1.w;
    }
    float4* ctx = (float4*)(xh + 512);
    ctx[tid]       = make_float4(c0.x * sinv, c0.y * sinv, c0.z * sinv, c0.w * sinv);
    ctx[tid + 256] = make_float4(c1.x * sinv, c1.y * sinv, c1.z * sinv, c1.w * sinv);

    // embedding for this step into x[0:512]
    if (tid < 128) {
        const int cap = captions[b * TT + t];
        const float4* er = (const float4*)(emb_table + (size_t)cap * EMBD);
        ((float4*)xh)[tid] = er[tid];
    }
}

// ---------------- GRU gate activations + h update --------------------------
__global__ __launch_bounds__(256) void gru_gates(
    int t, const float* __restrict__ b_ih, const float* __restrict__ b_hh)
{
    int idx = blockIdx.x * 256 + threadIdx.x;
    if (idx >= BATCH * DECD) return;
    int b = idx >> 9, d = idx & 511;
    const float* gi = g_gates + (size_t)b * GATE_N;
    const float* gh = g_gates + (size_t)BATCH * GATE_N + (size_t)b * GATE_N;
    float rr = (gi[d] + b_ih[d]) + (gh[d] + b_hh[d]);
    float zz = (gi[512 + d] + b_ih[512 + d]) + (gh[512 + d] + b_hh[512 + d]);
    float inp = gi[1024 + d] + b_ih[1024 + d];
    float hnp = gh[1024 + d] + b_hh[1024 + d];
    float r = 1.f / (1.f + expf(-rr));
    float z = 1.f / (1.f + expf(-zz));
    float n = tanhf(inp + r * hnp);
    float* xh = g_xh + (size_t)b * XH_W;
    float hold = xh[2560 + d];
    float hnew = (1.f - z) * n + z * hold;
    xh[2560 + d] = hnew;
    g_hall[((size_t)t * BATCH + b) * DECD + d] = hnew;
}

__global__ void write_caplens(const int* __restrict__ caplens, float* __restrict__ out, int n)
{
    int i = threadIdx.x;
    if (i < n && i < BATCH) out[i] = (float)(caplens[i] - 1);
}

// ---------------- host ----------------
extern "C" void kernel_launch(void* const* d_in, const int* in_sizes, int n_in,
                              void* d_out, int out_size)
{
    const float* enc       = (const float*)d_in[0];
    const int*   captions  = (const int*)  d_in[1];
    const int*   caplens   = (const int*)  d_in[2];
    const float* emb_table = (const float*)d_in[3];
    const float* W_enc     = (const float*)d_in[4];
    const float* b_enc     = (const float*)d_in[5];
    const float* W_dec     = (const float*)d_in[6];
    const float* b_dec     = (const float*)d_in[7];
    const float* w_full    = (const float*)d_in[8];
    const float* b_full    = (const float*)d_in[9];
    const float* W_ih      = (const float*)d_in[10];
    const float* b_ih      = (const float*)d_in[11];
    const float* W_hh      = (const float*)d_in[12];
    const float* b_hh      = (const float*)d_in[13];
    const float* W_fc      = (const float*)d_in[14];
    const float* b_fc      = (const float*)d_in[15];
    float* out = (float*)d_out;

    float *att1p, *xhp, *hallp;
    cudaGetSymbolAddress((void**)&att1p, g_att1);
    cudaGetSymbolAddress((void**)&xhp, g_xh);
    cudaGetSymbolAddress((void**)&hallp, g_hall);

    // h0 = 0 (one-time)
    zerok<<<(BATCH * XH_W + 255) / 256, 256>>>(xhp, BATCH * XH_W);

    // att1 = enc @ W_enc^T + b_enc : [12544,2048]x[2048,512]  (tf32 MMA)
    gemm_tf32<0><<<dim3(98, 8), 256>>>(enc, ENCD, W_enc, ENCD, b_enc, att1p,
                                       BATCH * PIX, ATTD, ENCD);

    for (int t = 0; t < NSTEP; t++) {
        attention_step<<<BATCH, 256>>>(t, enc, captions, emb_table,
                                       W_dec, b_dec, w_full, b_full);
        gru_gemms<<<dim3(24, 2, 10), 128>>>(xhp, W_ih, W_hh);
        gru_gates<<<(BATCH * DECD + 255) / 256, 256>>>(t, b_ih, b_hh);
    }

    // logits = h_all @ W_fc^T + b_fc, stored as [b, t, v]  (tf32 MMA)
    gemm_tf32<1><<<dim3(16, 469), 256>>>(hallp, DECD, W_fc, DECD, b_fc, out,
                                         NSTEP * BATCH, VOC, DECD);

    long long NLOG = (long long)BATCH * NSTEP * VOC;
    if ((long long)out_size > NLOG) {
        int rem = (int)((long long)out_size - NLOG);
        write_caplens<<<1, 64>>>(caplens, out + NLOG, rem);
    }
}